// round 3
// baseline (speedup 1.0000x reference)
#include <cuda_runtime.h>

// VectorQuantizer: z_e [32,64,64,64] f32, codebook [512,64] f32.
// row n (n = b*4096 + h*64 + w) reads z_e[b, :, h, w] (stride 4096),
// argmin_k ( ||z||^2 + ||e_k||^2 - 2 z.e_k ), output codebook row contiguous.
//
// R2: d-pair f32x2 packing (no lane duplication -> half the z registers),
// 2 rows per thread (each codebook LDS.128 feeds 4 FFMA2), row-major smem codebook.

#define N_ROWS   131072
#define K_CODES  512
#define D_DIM    64
#define ZQ_ELEMS (N_ROWS * D_DIM)   // 8388608
#define ROWS_PER_CTA 512            // 256 threads x 2 rows

__device__ int g_idx[N_ROWS];

__device__ __forceinline__ unsigned long long pack2(float lo, float hi) {
    unsigned long long r;
    asm("mov.b64 %0, {%1, %2};" : "=l"(r) : "f"(lo), "f"(hi));
    return r;
}
__device__ __forceinline__ void fma2(unsigned long long &acc,
                                     unsigned long long a,
                                     unsigned long long b) {
    // packed fp32x2 FMA: acc.lo += a.lo*b.lo ; acc.hi += a.hi*b.hi
    asm("fma.rn.f32x2 %0, %1, %2, %3;" : "=l"(acc) : "l"(a), "l"(b), "l"(acc));
}
__device__ __forceinline__ void unpack2(unsigned long long v, float &lo, float &hi) {
    asm("mov.b64 {%0, %1}, %2;" : "=f"(lo), "=f"(hi) : "l"(v));
}

extern __shared__ float sh[];  // [32768] codebook row-major + [512] norms

__global__ void __launch_bounds__(256, 1)
vq_main(const float* __restrict__ z_e, const float* __restrict__ cb,
        float* __restrict__ fidx_out) {
    const int tid = threadIdx.x;

    // --- stage codebook row-major into smem (vectorized, coalesced) ---
    {
        const float4* src = reinterpret_cast<const float4*>(cb);
        float4* dst = reinterpret_cast<float4*>(sh);
#pragma unroll
        for (int i = 0; i < (K_CODES * D_DIM / 4) / 256; i++)
            dst[i * 256 + tid] = src[i * 256 + tid];
    }
    __syncthreads();

    // --- code norms, sequential-d fp32 ---
    float* norms = sh + K_CODES * D_DIM;
    for (int k = tid; k < K_CODES; k += 256) {
        const float* e = sh + k * D_DIM;
        float s = 0.0f;
#pragma unroll 8
        for (int d = 0; d < D_DIM; d++)
            s = __fadd_rn(s, __fmul_rn(e[d], e[d]));
        norms[k] = s;
    }
    __syncthreads();

    // --- this thread's two rows (warp-coalesced gmem reads) ---
    const int rowA = blockIdx.x * ROWS_PER_CTA + tid;
    const int rowB = rowA + 256;

    unsigned long long zA[D_DIM / 2], zB[D_DIM / 2];
    float znA = 0.0f, znB = 0.0f;
    {
        const long baseA = (long)(rowA >> 12) * 262144 + (rowA & 4095);
        const long baseB = (long)(rowB >> 12) * 262144 + (rowB & 4095);
#pragma unroll
        for (int j = 0; j < D_DIM / 2; j++) {
            float a0 = z_e[baseA + (long)(2 * j)     * 4096];
            float a1 = z_e[baseA + (long)(2 * j + 1) * 4096];
            znA = __fadd_rn(znA, __fmul_rn(a0, a0));
            znA = __fadd_rn(znA, __fmul_rn(a1, a1));
            zA[j] = pack2(a0, a1);
            float b0 = z_e[baseB + (long)(2 * j)     * 4096];
            float b1 = z_e[baseB + (long)(2 * j + 1) * 4096];
            znB = __fadd_rn(znB, __fmul_rn(b0, b0));
            znB = __fadd_rn(znB, __fmul_rn(b1, b1));
            zB[j] = pack2(b0, b1);
        }
    }

    // --- main loop: 256 code-pairs; 32 LDS.128 + 128 FFMA2 per iter ---
    float bestA = 3.4e38f, bestB = 3.4e38f;
    int bkA = 0, bkB = 0;
#pragma unroll 1
    for (int kp = 0; kp < K_CODES / 2; kp++) {
        const double2* e0p = reinterpret_cast<const double2*>(sh + (2 * kp) * D_DIM);
        const double2* e1p = e0p + (D_DIM / 4);     // next code row
        unsigned long long aA0 = 0ULL, aA1 = 0ULL;  // row A vs codes 2kp, 2kp+1
        unsigned long long aB0 = 0ULL, aB1 = 0ULL;  // row B vs codes 2kp, 2kp+1
#pragma unroll
        for (int dd = 0; dd < D_DIM / 4; dd++) {    // 16 iters, 2 d-pairs each
            double2 e0 = e0p[dd];                   // code 2kp,  dims 4dd..4dd+3
            double2 e1 = e1p[dd];                   // code 2kp+1
            unsigned long long za0 = zA[2 * dd], za1 = zA[2 * dd + 1];
            unsigned long long zb0 = zB[2 * dd], zb1 = zB[2 * dd + 1];
            fma2(aA0, za0, __double_as_longlong(e0.x));
            fma2(aA1, za0, __double_as_longlong(e1.x));
            fma2(aB0, zb0, __double_as_longlong(e0.x));
            fma2(aB1, zb0, __double_as_longlong(e1.x));
            fma2(aA0, za1, __double_as_longlong(e0.y));
            fma2(aA1, za1, __double_as_longlong(e1.y));
            fma2(aB0, zb1, __double_as_longlong(e0.y));
            fma2(aB1, zb1, __double_as_longlong(e1.y));
        }
        float n0 = norms[2 * kp], n1 = norms[2 * kp + 1];
        float lo, hi, dot, s;

        unpack2(aA0, lo, hi); dot = __fadd_rn(lo, hi);
        s = __fadd_rn(__fadd_rn(znA, n0), __fmul_rn(-2.0f, dot));
        if (s < bestA) { bestA = s; bkA = 2 * kp; }
        unpack2(aA1, lo, hi); dot = __fadd_rn(lo, hi);
        s = __fadd_rn(__fadd_rn(znA, n1), __fmul_rn(-2.0f, dot));
        if (s < bestA) { bestA = s; bkA = 2 * kp + 1; }

        unpack2(aB0, lo, hi); dot = __fadd_rn(lo, hi);
        s = __fadd_rn(__fadd_rn(znB, n0), __fmul_rn(-2.0f, dot));
        if (s < bestB) { bestB = s; bkB = 2 * kp; }
        unpack2(aB1, lo, hi); dot = __fadd_rn(lo, hi);
        s = __fadd_rn(__fadd_rn(znB, n1), __fmul_rn(-2.0f, dot));
        if (s < bestB) { bestB = s; bkB = 2 * kp + 1; }
    }

    g_idx[rowA] = bkA;
    g_idx[rowB] = bkB;
    if (fidx_out) {
        fidx_out[rowA] = (float)bkA;
        fidx_out[rowB] = (float)bkB;
    }
}

// --- gather: out[n*64+d] = cb[idx[n]*64+d], fully coalesced via float4 ---
__global__ void vq_gather(const float4* __restrict__ cb4, float4* __restrict__ out4) {
    int g = blockIdx.x * 256 + threadIdx.x;   // 0 .. 2097151
    int n = g >> 4;
    int j = g & 15;
    out4[g] = cb4[(g_idx[n] << 4) + j];
}

extern "C" void kernel_launch(void* const* d_in, const int* in_sizes, int n_in,
                              void* d_out, int out_size) {
    const float* z_e = (const float*)d_in[0];
    const float* cb  = (const float*)d_in[1];
    if (n_in >= 2 && in_sizes[0] == K_CODES * D_DIM) {  // defensive swap
        const float* t = z_e; z_e = cb; cb = t;
    }
    float* out = (float*)d_out;

    const int smem_bytes = (K_CODES * D_DIM + K_CODES) * sizeof(float); // 133120
    cudaFuncSetAttribute(vq_main, cudaFuncAttributeMaxDynamicSharedMemorySize,
                         smem_bytes);

    float* fidx = (out_size > ZQ_ELEMS) ? out + ZQ_ELEMS : nullptr;

    vq_main<<<N_ROWS / ROWS_PER_CTA, 256, smem_bytes>>>(z_e, cb, fidx);
    vq_gather<<<ZQ_ELEMS / 4 / 256, 256>>>((const float4*)cb, (float4*)out);
}

// round 5
// speedup vs baseline: 1.7594x; 1.7594x over previous
#include <cuda_runtime.h>
#include <cstdint>

// VectorQuantizer via mma.sync tf32 (base PTX, works on sm_103 non-'a' target)
// + exact fp32 refine of near-tie rows. Codebook kept exact in smem.

#define N_ROWS   131072
#define K_CODES  512
#define D_DIM    64
#define ZQ_ELEMS (N_ROWS * D_DIM)
#define TILE_M   128
#define NTILES   (N_ROWS / TILE_M)   // 1024
#define THREADS  256
#define GRID     152
#define EPS      2e-4f
#define PCB      68                  // padded floats per code row (bank-safe)
#define PZ       65                  // padded floats per z row

// smem float offsets
#define O_CB   0                      // 512*68 = 34816
#define O_Z    34816                  // 128*65 = 8320
#define O_NRM  43136                  // 512
#define O_ZN   43648                  // 128
#define O_WIN  43776                  // 128 (int)
#define O_LIST 43904                  // 128 (int)
#define O_CNT  44032                  // 1 (int)
#define SMEM_F 44036
#define SMEM_BYTES (SMEM_F * 4)       // 176144

__device__ __forceinline__ uint32_t f2tf32(float f) {
    uint32_t r;
    asm("cvt.rna.tf32.f32 %0, %1;" : "=r"(r) : "f"(f));
    return r;
}
__device__ __forceinline__ void mma_tf32(float& c0, float& c1, float& c2, float& c3,
                                         uint32_t a0, uint32_t a1, uint32_t a2, uint32_t a3,
                                         uint32_t b0, uint32_t b1) {
    asm volatile(
        "mma.sync.aligned.m16n8k8.row.col.f32.tf32.tf32.f32 "
        "{%0,%1,%2,%3}, {%4,%5,%6,%7}, {%8,%9}, {%0,%1,%2,%3};"
        : "+f"(c0), "+f"(c1), "+f"(c2), "+f"(c3)
        : "r"(a0), "r"(a1), "r"(a2), "r"(a3), "r"(b0), "r"(b1));
}

__global__ void __launch_bounds__(THREADS, 1)
vq_mma(const float* __restrict__ z_e, const float* __restrict__ cb,
       float* __restrict__ out, float* __restrict__ fidx) {
    extern __shared__ float sh[];
    float* sCB  = sh + O_CB;
    float* sZ   = sh + O_Z;
    float* sNrm = sh + O_NRM;
    float* sZn  = sh + O_ZN;
    int*   sWin = (int*)(sh + O_WIN);
    int*   sLst = (int*)(sh + O_LIST);
    int*   sCnt = (int*)(sh + O_CNT);

    const int tid = threadIdx.x, wid = tid >> 5, lid = tid & 31;
    const int qid = lid & 3, gid = lid >> 2;   // quad id / group id in mma frag

    // ---- stage exact codebook into padded smem (once) ----
    {
        const float4* src = (const float4*)cb;
#pragma unroll
        for (int i = 0; i < 32; i++) {
            int e = i * THREADS + tid;         // 0..8191 float4s
            int k = e >> 4, j = e & 15;
            *(float4*)(sCB + k * PCB + 4 * j) = src[e];
        }
    }
    __syncthreads();
    // ---- code norms (sequential-d fp32, ref order) ----
    for (int k = tid; k < K_CODES; k += THREADS) {
        const float* e = sCB + k * PCB;
        float s = 0.0f;
#pragma unroll 8
        for (int d = 0; d < D_DIM; d++)
            s = __fadd_rn(s, __fmul_rn(e[d], e[d]));
        sNrm[k] = s;
    }
    __syncthreads();

    for (int tile = blockIdx.x; tile < NTILES; tile += GRID) {
        __syncthreads();   // protect sZ/sWin reuse across iterations
        {   // stage z tile -> sZ[row][c] (pad 65)
            const int row0 = tile * TILE_M;
            const float4* z4 = (const float4*)(z_e + (long)(row0 >> 12) * 262144
                                               + (row0 & 4095));
#pragma unroll
            for (int m = 0; m < 8; m++) {
                int q = tid + THREADS * m;
                int c = q >> 5, i4 = q & 31;
                float4 v = z4[c * 1024 + i4];
                int r = i4 * 4;
                sZ[(r + 0) * PZ + c] = v.x;
                sZ[(r + 1) * PZ + c] = v.y;
                sZ[(r + 2) * PZ + c] = v.z;
                sZ[(r + 3) * PZ + c] = v.w;
            }
        }
        if (tid == 0) *sCnt = 0;
        __syncthreads();
        if (tid < TILE_M) {   // ||z||^2, sequential-d
            const float* zr = sZ + tid * PZ;
            float s = 0.0f;
#pragma unroll 8
            for (int d = 0; d < D_DIM; d++)
                s = __fadd_rn(s, __fmul_rn(zr[d], zr[d]));
            sZn[tid] = s;
        }
        __syncthreads();

        // ---- mma + fused argmin: warp handles 16 rows ----
        {
            const int rb = wid * 16;
            uint32_t A[8][4];
#pragma unroll
            for (int ks = 0; ks < 8; ks++) {
                const float* r0 = sZ + (rb + gid) * PZ + ks * 8 + qid;
                const float* r1 = r0 + 8 * PZ;
                A[ks][0] = f2tf32(r0[0]);
                A[ks][1] = f2tf32(r1[0]);
                A[ks][2] = f2tf32(r0[4]);
                A[ks][3] = f2tf32(r1[4]);
            }
            float m1a = 3.4e38f, m2a = 3.4e38f, m1b = 3.4e38f, m2b = 3.4e38f;
            int k1a = 0, k1b = 0;
            const float2* nrm2 = (const float2*)sNrm;
#pragma unroll 1
            for (int nt = 0; nt < 64; nt++) {
                const float* bp = sCB + (nt * 8 + gid) * PCB + qid;
                float c0 = 0, c1 = 0, c2 = 0, c3 = 0;      // even ks chain
                float d0 = 0, d1 = 0, d2 = 0, d3 = 0;      // odd ks chain
#pragma unroll
                for (int ks = 0; ks < 8; ks += 2) {
                    uint32_t b0 = f2tf32(bp[ks * 8]);
                    uint32_t b1 = f2tf32(bp[ks * 8 + 4]);
                    uint32_t b2 = f2tf32(bp[ks * 8 + 8]);
                    uint32_t b3 = f2tf32(bp[ks * 8 + 12]);
                    mma_tf32(c0, c1, c2, c3, A[ks][0], A[ks][1], A[ks][2], A[ks][3], b0, b1);
                    mma_tf32(d0, d1, d2, d3, A[ks + 1][0], A[ks + 1][1], A[ks + 1][2], A[ks + 1][3], b2, b3);
                }
                float2 nk = nrm2[nt * 4 + qid];
                int n0 = nt * 8 + 2 * qid;
                float u;
                u = __fmaf_rn(-2.0f, c0 + d0, nk.x);
                { bool p = u < m1a; m2a = p ? m1a : fminf(m2a, u); m1a = p ? u : m1a; k1a = p ? n0 : k1a; }
                u = __fmaf_rn(-2.0f, c1 + d1, nk.y);
                { bool p = u < m1a; m2a = p ? m1a : fminf(m2a, u); m1a = p ? u : m1a; k1a = p ? n0 + 1 : k1a; }
                u = __fmaf_rn(-2.0f, c2 + d2, nk.x);
                { bool p = u < m1b; m2b = p ? m1b : fminf(m2b, u); m1b = p ? u : m1b; k1b = p ? n0 : k1b; }
                u = __fmaf_rn(-2.0f, c3 + d3, nk.y);
                { bool p = u < m1b; m2b = p ? m1b : fminf(m2b, u); m1b = p ? u : m1b; k1b = p ? n0 + 1 : k1b; }
            }
            // merge across the 4 lanes holding this row's columns
#pragma unroll
            for (int off = 1; off <= 2; off <<= 1) {
                float om1 = __shfl_xor_sync(0xffffffffu, m1a, off);
                float om2 = __shfl_xor_sync(0xffffffffu, m2a, off);
                int   ok1 = __shfl_xor_sync(0xffffffffu, k1a, off);
                float nm2 = fminf(fmaxf(m1a, om1), fminf(m2a, om2));
                if (om1 < m1a || (om1 == m1a && ok1 < k1a)) { m1a = om1; k1a = ok1; }
                m2a = nm2;
                om1 = __shfl_xor_sync(0xffffffffu, m1b, off);
                om2 = __shfl_xor_sync(0xffffffffu, m2b, off);
                ok1 = __shfl_xor_sync(0xffffffffu, k1b, off);
                nm2 = fminf(fmaxf(m1b, om1), fminf(m2b, om2));
                if (om1 < m1b || (om1 == m1b && ok1 < k1b)) { m1b = om1; k1b = ok1; }
                m2b = nm2;
            }
            if (qid == 0) {
                int rA = rb + gid, rB = rA + 8;
                sWin[rA] = k1a;
                sWin[rB] = k1b;
                if (m2a - m1a < EPS) sLst[atomicAdd(sCnt, 1)] = rA;
                if (m2b - m1b < EPS) sLst[atomicAdd(sCnt, 1)] = rB;
            }
        }
        __syncthreads();

        // ---- exact fp32 refine of flagged rows (one warp per row) ----
        {
            const int cnt = *sCnt;
            for (int fi = wid; fi < cnt; fi += 8) {
                const int row = sLst[fi];
                const float zn = sZn[row];
                const float* zr = sZ + row * PZ;
                unsigned long long key = 0xffffffffffffffffULL;
#pragma unroll 1
                for (int kk = 0; kk < 16; kk++) {
                    int k = kk * 32 + lid;
                    const float4* e4 = (const float4*)(sCB + k * PCB);
                    float aE = 0.0f, aO = 0.0f;
#pragma unroll
                    for (int j = 0; j < 16; j++) {
                        float4 e = e4[j];
                        aE = __fmaf_rn(zr[4 * j],     e.x, aE);
                        aO = __fmaf_rn(zr[4 * j + 1], e.y, aO);
                        aE = __fmaf_rn(zr[4 * j + 2], e.z, aE);
                        aO = __fmaf_rn(zr[4 * j + 3], e.w, aO);
                    }
                    float s = __fadd_rn(__fadd_rn(zn, sNrm[k]),
                                        __fmul_rn(-2.0f, __fadd_rn(aE, aO)));
                    unsigned long long c =
                        ((unsigned long long)__float_as_uint(s) << 32) | (unsigned)k;
                    if (c < key) key = c;   // s > 0 always -> bit order == value order
                }
#pragma unroll
                for (int off = 16; off > 0; off >>= 1) {
                    unsigned long long o = __shfl_xor_sync(0xffffffffu, key, off);
                    if (o < key) key = o;
                }
                if (lid == 0) sWin[row] = (int)(key & 0xffffffffu);
            }
        }
        __syncthreads();

        // ---- fused gather write (+ optional indices) ----
        {
            float4* out4 = (float4*)out + (size_t)tile * 2048;
#pragma unroll
            for (int m = 0; m < 8; m++) {
                int q = tid + THREADS * m;
                int n = q >> 4, j = q & 15;
                out4[q] = *(const float4*)(sCB + sWin[n] * PCB + 4 * j);
            }
            if (fidx && tid < TILE_M)
                fidx[tile * TILE_M + tid] = (float)sWin[tid];
        }
    }
}

extern "C" void kernel_launch(void* const* d_in, const int* in_sizes, int n_in,
                              void* d_out, int out_size) {
    const float* z_e = (const float*)d_in[0];
    const float* cb  = (const float*)d_in[1];
    if (n_in >= 2 && in_sizes[0] == K_CODES * D_DIM) {
        const float* t = z_e; z_e = cb; cb = t;
    }
    float* out = (float*)d_out;
    float* fidx = (out_size > ZQ_ELEMS) ? out + ZQ_ELEMS : nullptr;

    cudaFuncSetAttribute(vq_mma, cudaFuncAttributeMaxDynamicSharedMemorySize,
                         SMEM_BYTES);
    vq_mma<<<GRID, THREADS, SMEM_BYTES>>>(z_e, cb, out, fidx);
}